// round 15
// baseline (speedup 1.0000x reference)
#include <cuda_runtime.h>
#include <math.h>

#define NA 192
#define TT 80
#define NC 5
#define THREADS 256
#define NTILE 21            // upper-triangular 32x32 tiles of 192x192
#define TPB 3               // tiles per block
#define NBLK (NTILE / TPB)  // 7
#define TP 33               // transpose tile pitch (conflict-free)

typedef unsigned long long u64;

__device__ float g_invpd[NA * NA];

__constant__ int c_bi[NTILE] = {0,0,0,0,0,0, 1,1,1,1,1, 2,2,2,2, 3,3,3, 4,4, 5};
__constant__ int c_bj[NTILE] = {0,1,2,3,4,5, 1,2,3,4,5, 2,3,4,5, 3,4,5, 4,5, 5};

#define PK2(dst, v)   asm("mov.b64 %0, {%1, %1};" : "=l"(dst) : "f"(v))
#define SUB2(d,a,b)   asm("sub.rn.f32x2 %0, %1, %2;" : "=l"(d) : "l"(a), "l"(b))
#define MUL2(d,a,b)   asm("mul.rn.f32x2 %0, %1, %2;" : "=l"(d) : "l"(a), "l"(b))
#define ADD2ACC(a,b)  asm("add.rn.f32x2 %0, %0, %1;" : "+l"(a) : "l"(b))
#define FMA2(d,a,b,c) asm("fma.rn.f32x2 %0, %1, %2, %3;" : "=l"(d) : "l"(a), "l"(b), "l"(c))
#define UNPK2(lo,hi,v) asm("mov.b64 {%0, %1}, %2;" : "=f"(lo), "=f"(hi) : "l"(v))

// closed-form min over the 5 collinear i-circles:
// d2min = d20 + t^2 - 2 t g, t = clamp(rint(g/s),0,4)*s = rint(sat(g/4s)*4)*s
__device__ __forceinline__ void jtail(float g, float d20, float s, float inv4s,
                                      float& macc)
{
    float c4;
    asm("mul.rn.sat.f32 %0, %1, %2;" : "=f"(c4) : "f"(g), "f"(inv4s));
    const float c  = rintf(c4 * 4.0f);         // {0,1,2,3,4}
    const float tt = c * s;
    const float rr = fmaf(-2.0f, g, tt);       // t - 2g
    macc = fminf(macc, fmaf(tt, rr, d20));
}

// ---- prep: 1/pd once (reused by all 80 timesteps) ----
__global__ void __launch_bounds__(256)
prep_kernel(const float* __restrict__ pd)
{
    const int k = blockIdx.x * 256 + threadIdx.x;   // < 36864 exactly
    float ip;
    asm("rcp.approx.f32 %0, %1;" : "=f"(ip) : "f"(pd[k]));
    g_invpd[k] = ip;
}

// ---- main fused kernel ----
__global__ void __launch_bounds__(THREADS)
veh_kernel(const float* __restrict__ traj,   // (NA, T, 4)
           const float* __restrict__ cent,   // (NA, NC, 4)
           float* __restrict__ out)
{
    const int t   = blockIdx.y;
    const int tid = threadIdx.x;

    __shared__ __align__(16) float swx0[NA], swy0[NA];   // base circle (c=0)
    __shared__ __align__(16) float shx[NA],  shy[NA];    // unit heading
    __shared__ __align__(16) float svx[NA],  svy[NA];    // step vector s*h
    __shared__ __align__(16) float ss[NA],   sinv4[NA];  // spacing, 1/(4s)
    __shared__ float tpen[32 * TP];
    __shared__ float tmsk[32 * TP];

    // ---- prologue: base circle + per-agent constants ----
    if (tid < NA) {
        const int a = tid;
        const float4 tr = *reinterpret_cast<const float4*>(traj + ((size_t)a * TT + t) * 4);
        float hx = tr.z, hy = tr.w;
        const float inv = rsqrtf(hx * hx + hy * hy);
        hx *= inv; hy *= inv;
        const float cx0 = cent[(size_t)a * NC * 4];           // c=0 x (cy == 0)
        const float cx1 = cent[((size_t)a * NC + 1) * 4];     // c=1 x
        swx0[a] = fmaf(hx, cx0, tr.x);
        swy0[a] = fmaf(hy, cx0, tr.y);
        shx[a]  = hx;
        shy[a]  = hy;
        const float sp = cx1 - cx0;    // circle spacing (> 0)
        svx[a]  = sp * hx;
        svy[a]  = sp * hy;
        ss[a]   = sp;
        sinv4[a] = 0.25f / sp;
    }
    __syncthreads();

    const int r = tid >> 3;          // local i row 0..31
    const int q = tid & 7;           // quad column 0..7
    const size_t tbase = (size_t)t * (NA * NA);
    const size_t moff  = (size_t)TT * (NA * NA);

    #pragma unroll 1
    for (int it = 0; it < TPB; ++it) {
        const int tile = blockIdx.x * TPB + it;
        const int bi = c_bi[tile];
        const int bj = c_bj[tile];
        const int i  = bi * 32 + r;
        const int j0 = bj * 32 + q * 4;

        // i-state packed
        u64 xi2, yi2, hx2, hy2;
        PK2(xi2, swx0[i]);
        PK2(yi2, swy0[i]);
        PK2(hx2, shx[i]);
        PK2(hy2, shy[i]);
        const float si    = ss[i];
        const float inv4i = sinv4[i];

        // j-quad loads (once per tile): 4 LDS.128
        const ulonglong2 xj = *reinterpret_cast<const ulonglong2*>(swx0 + j0);
        const ulonglong2 yj = *reinterpret_cast<const ulonglong2*>(swy0 + j0);
        const ulonglong2 vx = *reinterpret_cast<const ulonglong2*>(svx + j0);
        const ulonglong2 vy = *reinterpret_cast<const ulonglong2*>(svy + j0);

        // invpd early (L2 latency hidden under main loop)
        const int idx = i * NA + j0;
        const float4 ip4 = *reinterpret_cast<const float4*>(g_invpd + idx);

        // lane A = (j0, j0+1), lane B = (j0+2, j0+3)
        u64 dxA, dyA, dxB, dyB, gA, gB, kA, kB, tA, d2A, d2B;
        SUB2(dxA, xj.x, xi2);
        SUB2(dyA, yj.x, yi2);
        SUB2(dxB, xj.y, xi2);
        SUB2(dyB, yj.y, yi2);
        MUL2(gA, hx2, dxA);  FMA2(gA, hy2, dyA, gA);    // g = h_i . Delta
        MUL2(gB, hx2, dxB);  FMA2(gB, hy2, dyB, gB);
        MUL2(kA, hx2, vx.x); FMA2(kA, hy2, vy.x, kA);   // kappa = h_i . (s_j h_j)
        MUL2(kB, hx2, vx.y); FMA2(kB, hy2, vy.y, kB);

        float m0 = 3.4e38f, m1 = 3.4e38f, m2 = 3.4e38f, m3 = 3.4e38f;

        #pragma unroll
        for (int d = 0; d < NC; ++d) {
            float ga, gb, da, db;

            MUL2(tA, dxA, dxA); FMA2(d2A, dyA, dyA, tA);
            MUL2(tA, dxB, dxB); FMA2(d2B, dyB, dyB, tA);

            UNPK2(ga, gb, gA); UNPK2(da, db, d2A);
            jtail(ga, da, si, inv4i, m0);
            jtail(gb, db, si, inv4i, m1);
            UNPK2(ga, gb, gB); UNPK2(da, db, d2B);
            jtail(ga, da, si, inv4i, m2);
            jtail(gb, db, si, inv4i, m3);

            if (d < NC - 1) {   // advance to next j circle
                ADD2ACC(dxA, vx.x); ADD2ACC(dyA, vy.x); ADD2ACC(gA, kA);
                ADD2ACC(dxB, vx.y); ADD2ACC(dyB, vy.y); ADD2ACC(gB, kB);
            }
        }

        const float mv[4] = {m0, m1, m2, m3};
        const float ipv[4] = {ip4.x, ip4.y, ip4.z, ip4.w};
        const bool diag = (bi == bj);

        float4 pen, msk;
        float* penp = &pen.x;
        float* mskp = &msk.x;
        #pragma unroll
        for (int k = 0; k < 4; ++k) {
            const float m2e = fmaxf(mv[k], 1e-30f);   // clamp + sqrt guard
            float sq;
            asm("sqrt.approx.f32 %0, %1;" : "=f"(sq) : "f"(m2e));
            penp[k] = fmaf(-sq, ipv[k], 1.0f);        // 1 - mind/p
            // mind <= p  <=>  pen >= 0 ; diagonal excluded by i != j
            bool coll = (penp[k] >= 0.0f);
            if (diag) coll = coll && (i != j0 + k);
            mskp[k] = coll ? 1.0f : 0.0f;
        }

        // direct tile write
        *reinterpret_cast<float4*>(out + tbase + idx) = pen;
        *reinterpret_cast<float4*>(out + moff + tbase + idx) = msk;

        // mirrored tile write (off-diagonal tiles only; block-uniform branch)
        if (!diag) {
            __syncthreads();    // protect tpen/tmsk reuse across iterations
            #pragma unroll
            for (int k = 0; k < 4; ++k) {
                tpen[(q * 4 + k) * TP + r] = penp[k];   // [local j][local i]
                tmsk[(q * 4 + k) * TP + r] = mskp[k];
            }
            __syncthreads();

            float4 vp, vm;
            float* vpp = &vp.x;
            float* vmp = &vm.x;
            #pragma unroll
            for (int k = 0; k < 4; ++k) {
                vpp[k] = tpen[r * TP + q * 4 + k];
                vmp[k] = tmsk[r * TP + q * 4 + k];
            }
            const int ot = (bj * 32 + r) * NA + bi * 32 + q * 4;
            *reinterpret_cast<float4*>(out + tbase + ot) = vp;
            *reinterpret_cast<float4*>(out + moff + tbase + ot) = vm;
        }
    }
}

extern "C" void kernel_launch(void* const* d_in, const int* in_sizes, int n_in,
                              void* d_out, int out_size)
{
    const float* traj = (const float*)d_in[0];   // (192,80,4)
    const float* cent = (const float*)d_in[1];   // (192,5,4)
    const float* pd   = (const float*)d_in[2];   // (192,192)

    prep_kernel<<<NA * NA / 256, 256>>>(pd);     // 144 blocks, ~0.5us

    dim3 grid(NBLK, TT);   // (7, 80) = 560 blocks
    veh_kernel<<<grid, THREADS>>>(traj, cent, (float*)d_out);
}

// round 16
// speedup vs baseline: 1.1355x; 1.1355x over previous
#include <cuda_runtime.h>
#include <math.h>

#define NA 192
#define TT 80
#define NC 5
#define THREADS 256
#define NTILE 21            // upper-triangular 32x32 tiles of 192x192
#define TPB 3               // tiles per block
#define NBLK (NTILE / TPB)  // 7
#define TP 33               // transpose tile pitch (conflict-free)
#define MAGIC 8388608.0f    // 2^23: RNE integer rounding via mantissa

typedef unsigned long long u64;

__constant__ int c_bi[NTILE] = {0,0,0,0,0,0, 1,1,1,1,1, 2,2,2,2, 3,3,3, 4,4, 5};
__constant__ int c_bj[NTILE] = {0,1,2,3,4,5, 1,2,3,4,5, 2,3,4,5, 3,4,5, 4,5, 5};

#define PK2(dst, v)   asm("mov.b64 %0, {%1, %1};" : "=l"(dst) : "f"(v))
#define SUB2(d,a,b)   asm("sub.rn.f32x2 %0, %1, %2;" : "=l"(d) : "l"(a), "l"(b))
#define MUL2(d,a,b)   asm("mul.rn.f32x2 %0, %1, %2;" : "=l"(d) : "l"(a), "l"(b))
#define ADD2ACC(a,b)  asm("add.rn.f32x2 %0, %0, %1;" : "+l"(a) : "l"(b))
#define FMA2(d,a,b,c) asm("fma.rn.f32x2 %0, %1, %2, %3;" : "=l"(d) : "l"(a), "l"(b), "l"(c))
#define UNPK2(lo,hi,v) asm("mov.b64 {%0, %1}, %2;" : "=f"(lo), "=f"(hi) : "l"(v))

// closed-form min over the 5 collinear i-circles, magic-constant rounding:
//   c4 = sat(g/(4s)); cm = rne(4*c4)+2^23 (in-mantissa); tt = cm*s - 2^23*s = c*s
//   d2min = d20 + tt*(tt - 2g)
__device__ __forceinline__ void jtail(float g, float d20, float si, float inv4i,
                                      float nMs, float& macc)
{
    float c4;
    asm("mul.rn.sat.f32 %0, %1, %2;" : "=f"(c4) : "f"(g), "f"(inv4i));
    const float cm = fmaf(c4, 4.0f, MAGIC);
    const float tt = fmaf(cm, si, nMs);          // = c * si, exact
    const float rr = fmaf(-2.0f, g, tt);         // t - 2g
    macc = fminf(macc, fmaf(tt, rr, d20));
}

// ---- single fused kernel ----
__global__ void __launch_bounds__(THREADS)
veh_kernel(const float* __restrict__ traj,   // (NA, T, 4)
           const float* __restrict__ cent,   // (NA, NC, 4)
           const float* __restrict__ pd,     // (NA, NA)
           float* __restrict__ out)
{
    const int t   = blockIdx.y;
    const int tid = threadIdx.x;

    __shared__ __align__(16) float swx0[NA], swy0[NA];   // base circle (c=0)
    __shared__ __align__(16) float shx[NA],  shy[NA];    // unit heading
    __shared__ __align__(16) float svx[NA],  svy[NA];    // step vector s*h
    __shared__ __align__(16) float ss[NA],   sinv4[NA];  // spacing, 1/(4s)
    __shared__ __align__(16) float snMs[NA];              // -2^23 * s
    __shared__ float tpen[32 * TP];
    __shared__ float tmsk[32 * TP];

    // ---- prologue: base circle + per-agent constants ----
    if (tid < NA) {
        const int a = tid;
        const float4 tr = *reinterpret_cast<const float4*>(traj + ((size_t)a * TT + t) * 4);
        float hx = tr.z, hy = tr.w;
        const float inv = rsqrtf(hx * hx + hy * hy);
        hx *= inv; hy *= inv;
        const float cx0 = cent[(size_t)a * NC * 4];           // c=0 x (cy == 0)
        const float cx1 = cent[((size_t)a * NC + 1) * 4];     // c=1 x
        swx0[a] = fmaf(hx, cx0, tr.x);
        swy0[a] = fmaf(hy, cx0, tr.y);
        shx[a]  = hx;
        shy[a]  = hy;
        const float sp = cx1 - cx0;    // circle spacing (> 0)
        svx[a]  = sp * hx;
        svy[a]  = sp * hy;
        ss[a]   = sp;
        sinv4[a] = 0.25f / sp;
        snMs[a]  = -MAGIC * sp;        // exact (exponent shift)
    }
    __syncthreads();

    const int r = tid >> 3;          // local i row 0..31
    const int q = tid & 7;           // quad column 0..7
    const size_t tbase = (size_t)t * (NA * NA);
    const size_t moff  = (size_t)TT * (NA * NA);

    #pragma unroll 1
    for (int it = 0; it < TPB; ++it) {
        const int tile = blockIdx.x * TPB + it;
        const int bi = c_bi[tile];
        const int bj = c_bj[tile];
        const int i  = bi * 32 + r;
        const int j0 = bj * 32 + q * 4;

        // i-state packed
        u64 xi2, yi2, hx2, hy2;
        PK2(xi2, swx0[i]);
        PK2(yi2, swy0[i]);
        PK2(hx2, shx[i]);
        PK2(hy2, shy[i]);
        const float si    = ss[i];
        const float inv4i = sinv4[i];
        const float nMsi  = snMs[i];

        // j-quad loads (once per tile): 4 LDS.128
        const ulonglong2 xj = *reinterpret_cast<const ulonglong2*>(swx0 + j0);
        const ulonglong2 yj = *reinterpret_cast<const ulonglong2*>(swy0 + j0);
        const ulonglong2 vx = *reinterpret_cast<const ulonglong2*>(svx + j0);
        const ulonglong2 vy = *reinterpret_cast<const ulonglong2*>(svy + j0);

        // pd early (L2 latency hidden under main loop)
        const int idx = i * NA + j0;
        const float4 p4 = *reinterpret_cast<const float4*>(pd + idx);

        // lane A = (j0, j0+1), lane B = (j0+2, j0+3)
        u64 dxA, dyA, dxB, dyB, gA, gB, kA, kB, tA, d2A, d2B;
        SUB2(dxA, xj.x, xi2);
        SUB2(dyA, yj.x, yi2);
        SUB2(dxB, xj.y, xi2);
        SUB2(dyB, yj.y, yi2);
        MUL2(gA, hx2, dxA);  FMA2(gA, hy2, dyA, gA);    // g = h_i . Delta
        MUL2(gB, hx2, dxB);  FMA2(gB, hy2, dyB, gB);
        MUL2(kA, hx2, vx.x); FMA2(kA, hy2, vy.x, kA);   // kappa = h_i . (s_j h_j)
        MUL2(kB, hx2, vx.y); FMA2(kB, hy2, vy.y, kB);

        float m0 = 3.4e38f, m1 = 3.4e38f, m2 = 3.4e38f, m3 = 3.4e38f;

        #pragma unroll
        for (int d = 0; d < NC; ++d) {
            float ga, gb, da, db;

            MUL2(tA, dxA, dxA); FMA2(d2A, dyA, dyA, tA);
            MUL2(tA, dxB, dxB); FMA2(d2B, dyB, dyB, tA);

            UNPK2(ga, gb, gA); UNPK2(da, db, d2A);
            jtail(ga, da, si, inv4i, nMsi, m0);
            jtail(gb, db, si, inv4i, nMsi, m1);
            UNPK2(ga, gb, gB); UNPK2(da, db, d2B);
            jtail(ga, da, si, inv4i, nMsi, m2);
            jtail(gb, db, si, inv4i, nMsi, m3);

            if (d < NC - 1) {   // advance to next j circle
                ADD2ACC(dxA, vx.x); ADD2ACC(dyA, vy.x); ADD2ACC(gA, kA);
                ADD2ACC(dxB, vx.y); ADD2ACC(dyB, vy.y); ADD2ACC(gB, kB);
            }
        }

        const float mv[4] = {m0, m1, m2, m3};
        const float pv[4] = {p4.x, p4.y, p4.z, p4.w};
        const bool diag = (bi == bj);

        float4 pen, msk;
        float* penp = &pen.x;
        float* mskp = &msk.x;
        #pragma unroll
        for (int k = 0; k < 4; ++k) {
            const float m2e = fmaxf(mv[k], 1e-30f);   // clamp + sqrt guard
            float sq, ip;
            asm("sqrt.approx.f32 %0, %1;" : "=f"(sq) : "f"(m2e));
            asm("rcp.approx.f32 %0, %1;"  : "=f"(ip) : "f"(pv[k]));
            penp[k] = fmaf(-sq, ip, 1.0f);            // 1 - mind/p
            // mind <= p  <=>  pen >= 0 ; diagonal excluded by i != j
            bool coll = (penp[k] >= 0.0f);
            if (diag) coll = coll && (i != j0 + k);
            mskp[k] = coll ? 1.0f : 0.0f;
        }

        // direct tile write
        *reinterpret_cast<float4*>(out + tbase + idx) = pen;
        *reinterpret_cast<float4*>(out + moff + tbase + idx) = msk;

        // mirrored tile write (off-diagonal tiles only; block-uniform branch)
        if (!diag) {
            __syncthreads();    // protect tpen/tmsk reuse across iterations
            #pragma unroll
            for (int k = 0; k < 4; ++k) {
                tpen[(q * 4 + k) * TP + r] = penp[k];   // [local j][local i]
                tmsk[(q * 4 + k) * TP + r] = mskp[k];
            }
            __syncthreads();

            float4 vp, vm;
            float* vpp = &vp.x;
            float* vmp = &vm.x;
            #pragma unroll
            for (int k = 0; k < 4; ++k) {
                vpp[k] = tpen[r * TP + q * 4 + k];
                vmp[k] = tmsk[r * TP + q * 4 + k];
            }
            const int ot = (bj * 32 + r) * NA + bi * 32 + q * 4;
            *reinterpret_cast<float4*>(out + tbase + ot) = vp;
            *reinterpret_cast<float4*>(out + moff + tbase + ot) = vm;
        }
    }
}

extern "C" void kernel_launch(void* const* d_in, const int* in_sizes, int n_in,
                              void* d_out, int out_size)
{
    const float* traj = (const float*)d_in[0];   // (192,80,4)
    const float* cent = (const float*)d_in[1];   // (192,5,4)
    const float* pd   = (const float*)d_in[2];   // (192,192)

    dim3 grid(NBLK, TT);   // (7, 80) = 560 blocks — single launch
    veh_kernel<<<grid, THREADS>>>(traj, cent, pd, (float*)d_out);
}